// round 3
// baseline (speedup 1.0000x reference)
#include <cuda_runtime.h>
#include <math.h>

// Problem constants
#define Bb 2
#define Ss 2048
#define Dd 1024
#define Hh 16
#define DEPTH 64
#define MROWS (Bb * Ss)                 // 4096

static const long long OUT_ELEMS  = (long long)Bb * Ss * Dd;          // 4,194,304
static const long long ATTN_ELEMS = (long long)Bb * Hh * Ss * Ss;     // 134,217,728

// ---------------- device scratch (no cudaMalloc allowed) ----------------
__device__ float g_Q[MROWS * Dd];
__device__ float g_K[MROWS * Dd];
__device__ float g_V[MROWS * Dd];
__device__ float g_Z[MROWS * Dd];
__device__ float g_attn[(size_t)Bb * Hh * Ss * Ss];   // 512 MB bss fallback
__device__ float g_out[MROWS * Dd];                   // fallback if d_out holds only attn

// ---------------------------------------------------------------
// Generic fp32 tiled GEMM: C[M,N] = A[M,K] @ B[K,N] + bias[N]
// BM=BN=64, BK=16, 256 threads, 4x4 per thread. All dims multiples of tile.
// ---------------------------------------------------------------
__global__ void gemm_bias_kernel(const float* __restrict__ A,
                                 const float* __restrict__ Bm,
                                 const float* __restrict__ bias,
                                 float* __restrict__ C,
                                 int M, int N, int K) {
    __shared__ float As[16][64];      // [k][m]
    __shared__ float Bs[16][64];      // [k][n]

    const int tx = threadIdx.x & 15;          // 0..15 -> n
    const int ty = threadIdx.x >> 4;          // 0..15 -> m
    const int row0 = blockIdx.y * 64;
    const int col0 = blockIdx.x * 64;

    float acc[4][4] = {};

    for (int k0 = 0; k0 < K; k0 += 16) {
        // load A tile 64x16 (transposed into As[k][m])
        #pragma unroll
        for (int i = threadIdx.x; i < 64 * 16; i += 256) {
            int m = i >> 4, kk = i & 15;
            As[kk][m] = A[(size_t)(row0 + m) * K + k0 + kk];
        }
        // load B tile 16x64
        #pragma unroll
        for (int i = threadIdx.x; i < 16 * 64; i += 256) {
            int kk = i >> 6, n = i & 63;
            Bs[kk][n] = Bm[(size_t)(k0 + kk) * N + col0 + n];
        }
        __syncthreads();

        #pragma unroll
        for (int kk = 0; kk < 16; kk++) {
            float a[4], b[4];
            #pragma unroll
            for (int i = 0; i < 4; i++) a[i] = As[kk][ty * 4 + i];
            #pragma unroll
            for (int j = 0; j < 4; j++) b[j] = Bs[kk][tx * 4 + j];
            #pragma unroll
            for (int i = 0; i < 4; i++)
                #pragma unroll
                for (int j = 0; j < 4; j++)
                    acc[i][j] = fmaf(a[i], b[j], acc[i][j]);
        }
        __syncthreads();
    }

    #pragma unroll
    for (int i = 0; i < 4; i++) {
        int r = row0 + ty * 4 + i;
        #pragma unroll
        for (int j = 0; j < 4; j++) {
            int c = col0 + tx * 4 + j;
            C[(size_t)r * N + c] = acc[i][j] + bias[c];
        }
    }
}

// ---------------------------------------------------------------
// logits[bh, q, k] = (Q[b,h,q,:] . K[b,h,k,:]) * 0.125 + min(1, m[q]+m[k])
// Q/K stored interleaved as (B, S, D) with head offset h*64.
// grid: (S/64, S/64, B*H); block 256
// ---------------------------------------------------------------
__global__ void logits_kernel(const float* __restrict__ Q,
                              const float* __restrict__ Kb,
                              const float* __restrict__ mask,
                              float* __restrict__ attn) {
    const int bh = blockIdx.z;
    const int b  = bh / Hh;
    const int h  = bh % Hh;
    const int q0 = blockIdx.y * 64;
    const int k0 = blockIdx.x * 64;

    __shared__ float Qs[64][DEPTH + 1];
    __shared__ float Ks[64][DEPTH + 1];

    const float* Qbase = Q  + (size_t)b * Ss * Dd + (size_t)h * DEPTH;
    const float* Kbase = Kb + (size_t)b * Ss * Dd + (size_t)h * DEPTH;

    #pragma unroll
    for (int i = threadIdx.x; i < 64 * 64; i += 256) {
        int r = i >> 6, d = i & 63;
        Qs[r][d] = Qbase[(size_t)(q0 + r) * Dd + d];
        Ks[r][d] = Kbase[(size_t)(k0 + r) * Dd + d];
    }
    __syncthreads();

    const int tx = threadIdx.x & 15;
    const int ty = threadIdx.x >> 4;

    float acc[4][4] = {};
    #pragma unroll
    for (int d = 0; d < DEPTH; d++) {
        float a[4], c[4];
        #pragma unroll
        for (int i = 0; i < 4; i++) a[i] = Qs[ty * 4 + i][d];
        #pragma unroll
        for (int j = 0; j < 4; j++) c[j] = Ks[tx * 4 + j][d];
        #pragma unroll
        for (int i = 0; i < 4; i++)
            #pragma unroll
            for (int j = 0; j < 4; j++)
                acc[i][j] = fmaf(a[i], c[j], acc[i][j]);
    }

    const float scale = 0.125f;   // 1/sqrt(64)
    #pragma unroll
    for (int i = 0; i < 4; i++) {
        int q = q0 + ty * 4 + i;
        float mq = mask[b * Ss + q];
        #pragma unroll
        for (int j = 0; j < 4; j++) {
            int k = k0 + tx * 4 + j;
            float m = fminf(1.0f, mq + mask[b * Ss + k]);
            attn[((size_t)bh * Ss + q) * Ss + k] = acc[i][j] * scale + m;
        }
    }
}

// ---------------------------------------------------------------
// In-place softmax over last dim (S=2048). 1 block (256 thr) per row.
// ---------------------------------------------------------------
__global__ void softmax_kernel(float* __restrict__ attn) {
    const size_t row = blockIdx.x;
    float* p = attn + row * (size_t)Ss;
    const int t = threadIdx.x;

    float v[8];
    float mx = -1e30f;
    #pragma unroll
    for (int i = 0; i < 8; i++) {
        v[i] = p[t + 256 * i];
        mx = fmaxf(mx, v[i]);
    }

    __shared__ float red[8];
    #pragma unroll
    for (int o = 16; o; o >>= 1) mx = fmaxf(mx, __shfl_xor_sync(0xffffffffu, mx, o));
    if ((t & 31) == 0) red[t >> 5] = mx;
    __syncthreads();
    mx = red[0];
    #pragma unroll
    for (int i = 1; i < 8; i++) mx = fmaxf(mx, red[i]);
    __syncthreads();

    float sum = 0.0f;
    #pragma unroll
    for (int i = 0; i < 8; i++) {
        v[i] = __expf(v[i] - mx);
        sum += v[i];
    }
    #pragma unroll
    for (int o = 16; o; o >>= 1) sum += __shfl_xor_sync(0xffffffffu, sum, o);
    if ((t & 31) == 0) red[t >> 5] = sum;
    __syncthreads();
    sum = 0.0f;
    #pragma unroll
    for (int i = 0; i < 8; i++) sum += red[i];

    const float inv = 1.0f / sum;
    #pragma unroll
    for (int i = 0; i < 8; i++) p[t + 256 * i] = v[i] * inv;
}

// ---------------------------------------------------------------
// Z[b, q, h*64+dd] = sum_k attn[bh,q,k] * V[b,k,h*64+dd]
// grid: (S/64, B*H); block 256. N=64 (full depth) per block.
// ---------------------------------------------------------------
__global__ void av_kernel(const float* __restrict__ attn,
                          const float* __restrict__ V,
                          float* __restrict__ Z) {
    const int bh = blockIdx.y;
    const int b  = bh / Hh;
    const int h  = bh % Hh;
    const int q0 = blockIdx.x * 64;

    const float* Ab = attn + (size_t)bh * Ss * Ss;
    const float* Vb = V + (size_t)b * Ss * Dd + (size_t)h * DEPTH;

    __shared__ float As[64][16 + 1];   // [q][k], padded vs bank conflicts
    __shared__ float Bs[16][64];       // [k][dd]

    const int tx = threadIdx.x & 15;
    const int ty = threadIdx.x >> 4;

    float acc[4][4] = {};

    for (int k0 = 0; k0 < Ss; k0 += 16) {
        #pragma unroll
        for (int i = threadIdx.x; i < 64 * 16; i += 256) {
            int r = i >> 4, kk = i & 15;
            As[r][kk] = Ab[(size_t)(q0 + r) * Ss + k0 + kk];
        }
        #pragma unroll
        for (int i = threadIdx.x; i < 16 * 64; i += 256) {
            int kk = i >> 6, dd = i & 63;
            Bs[kk][dd] = Vb[(size_t)(k0 + kk) * Dd + dd];
        }
        __syncthreads();

        #pragma unroll
        for (int kk = 0; kk < 16; kk++) {
            float a[4], c[4];
            #pragma unroll
            for (int i = 0; i < 4; i++) a[i] = As[ty * 4 + i][kk];
            #pragma unroll
            for (int j = 0; j < 4; j++) c[j] = Bs[kk][tx * 4 + j];
            #pragma unroll
            for (int i = 0; i < 4; i++)
                #pragma unroll
                for (int j = 0; j < 4; j++)
                    acc[i][j] = fmaf(a[i], c[j], acc[i][j]);
        }
        __syncthreads();
    }

    #pragma unroll
    for (int i = 0; i < 4; i++) {
        int q = q0 + ty * 4 + i;
        #pragma unroll
        for (int j = 0; j < 4; j++) {
            Z[(size_t)(b * Ss + q) * Dd + (size_t)h * DEPTH + tx * 4 + j] = acc[i][j];
        }
    }
}

// ---------------------------------------------------------------
extern "C" void kernel_launch(void* const* d_in, const int* in_sizes, int n_in,
                              void* d_out, int out_size) {
    const float* x    = (const float*)d_in[0];
    const float* mask = (const float*)d_in[1];
    const float* Wq   = (const float*)d_in[2];
    const float* bq   = (const float*)d_in[3];
    const float* Wk   = (const float*)d_in[4];
    const float* bk   = (const float*)d_in[5];
    const float* Wv   = (const float*)d_in[6];
    const float* bv   = (const float*)d_in[7];
    const float* Wo   = (const float*)d_in[8];
    const float* bo   = (const float*)d_in[9];

    float *Qb, *Kb, *Vb, *Zb, *attn_scr, *out_scr;
    cudaGetSymbolAddress((void**)&Qb, g_Q);
    cudaGetSymbolAddress((void**)&Kb, g_K);
    cudaGetSymbolAddress((void**)&Vb, g_V);
    cudaGetSymbolAddress((void**)&Zb, g_Z);
    cudaGetSymbolAddress((void**)&attn_scr, g_attn);
    cudaGetSymbolAddress((void**)&out_scr, g_out);

    // Decide where out / attn live based on out_size (reference returns (out, attn)).
    float* out_ptr;
    float* attn_ptr;
    const long long osz = (long long)out_size;
    if (osz >= OUT_ELEMS + ATTN_ELEMS) {
        out_ptr  = (float*)d_out;
        attn_ptr = (float*)d_out + OUT_ELEMS;
    } else if (osz >= ATTN_ELEMS) {          // only attn fits -> attn is the output
        attn_ptr = (float*)d_out;
        out_ptr  = out_scr;
    } else {                                  // only out fits
        out_ptr  = (float*)d_out;
        attn_ptr = attn_scr;
    }

    const dim3 blk(256);

    // Q, K, V projections: (4096x1024) @ (1024x1024)
    {
        dim3 grid(Dd / 64, MROWS / 64);
        gemm_bias_kernel<<<grid, blk>>>(x, Wq, bq, Qb, MROWS, Dd, Dd);
        gemm_bias_kernel<<<grid, blk>>>(x, Wk, bk, Kb, MROWS, Dd, Dd);
        gemm_bias_kernel<<<grid, blk>>>(x, Wv, bv, Vb, MROWS, Dd, Dd);
    }

    // logits + mask
    {
        dim3 grid(Ss / 64, Ss / 64, Bb * Hh);
        logits_kernel<<<grid, blk>>>(Qb, Kb, mask, attn_ptr);
    }

    // softmax rows
    softmax_kernel<<<(unsigned)(Bb * Hh * Ss), blk>>>(attn_ptr);

    // Z = attn @ V
    {
        dim3 grid(Ss / 64, Bb * Hh);
        av_kernel<<<grid, blk>>>(attn_ptr, Vb, Zb);
    }

    // out = Z @ Wo + bo
    {
        dim3 grid(Dd / 64, MROWS / 64);
        gemm_bias_kernel<<<grid, blk>>>(Zb, Wo, bo, out_ptr, MROWS, Dd, Dd);
    }
}

// round 4
// speedup vs baseline: 3.4067x; 3.4067x over previous
#include <cuda_runtime.h>
#include <math.h>

// Problem constants
#define Bb 2
#define Ss 2048
#define Dd 1024
#define Hh 16
#define DEPTH 64
#define MROWS (Bb * Ss)                 // 4096

static const long long OUT_ELEMS  = (long long)Bb * Ss * Dd;          // 4,194,304
static const long long ATTN_ELEMS = (long long)Bb * Hh * Ss * Ss;     // 134,217,728

// ---------------- device scratch (no cudaMalloc allowed) ----------------
__device__ float g_Q[MROWS * Dd];
__device__ float g_K[MROWS * Dd];
__device__ float g_V[MROWS * Dd];
__device__ float g_Z[MROWS * Dd];
__device__ float g_attn[(size_t)Bb * Hh * Ss * Ss];   // 512 MB bss fallback
__device__ float g_out[MROWS * Dd];                   // fallback if d_out holds only attn

// ---------------- tf32 helpers ----------------
__device__ __forceinline__ unsigned f2tf(float f) {
    unsigned u;
    asm("cvt.rna.tf32.f32 %0, %1;" : "=r"(u) : "f"(f));
    return u;
}

// D += A(16x8) * B(8x8), tf32 in, fp32 accum. row.col layout.
__device__ __forceinline__ void mma8(float* d, const unsigned* a, const unsigned* b) {
    asm volatile(
        "mma.sync.aligned.m16n8k8.row.col.f32.tf32.tf32.f32 "
        "{%0,%1,%2,%3}, {%4,%5,%6,%7}, {%8,%9}, {%0,%1,%2,%3};\n"
        : "+f"(d[0]), "+f"(d[1]), "+f"(d[2]), "+f"(d[3])
        : "r"(a[0]), "r"(a[1]), "r"(a[2]), "r"(a[3]),
          "r"(b[0]), "r"(b[1]));
}

// ---------------------------------------------------------------
// Tensor-core GEMM: C[M,N] = A[M,K] @ B[K,N] + bias[N]
// BM=128, BN=128, BK=16, 256 threads (8 warps, 2x4), warp tile 64x32.
// Double buffered. Smem pads chosen for conflict-free fragment loads:
//   As stride 20 (20*gid+tig distinct banks), Bs stride 136 (8*tig+gid distinct).
// ---------------------------------------------------------------
__global__ void __launch_bounds__(256) gemm_tc(
    const float* __restrict__ A, const float* __restrict__ Bm,
    const float* __restrict__ bias, float* __restrict__ C,
    int M, int N, int K)
{
    __shared__ unsigned As[2][128][20];
    __shared__ unsigned Bs[2][16][136];

    const int tid  = threadIdx.x;
    const int lane = tid & 31;
    const int wid  = tid >> 5;
    const int gid  = lane >> 2;       // 0..7
    const int tig  = lane & 3;        // 0..3
    const int wm   = wid & 1;         // 2 warps over M
    const int wn   = wid >> 1;        // 4 warps over N
    const int row0 = blockIdx.y * 128;
    const int col0 = blockIdx.x * 128;

    const int ar = tid >> 2;          // A load: rows ar, ar+64
    const int ac = (tid & 3) * 4;
    const int br = tid >> 5;          // B load: rows br, br+8
    const int bc = (tid & 31) * 4;

    float acc[4][4][4] = {};

    // initial tile
    {
        float4 v0 = *(const float4*)&A[(size_t)(row0 + ar) * K + ac];
        float4 v1 = *(const float4*)&A[(size_t)(row0 + ar + 64) * K + ac];
        As[0][ar][ac+0]=f2tf(v0.x); As[0][ar][ac+1]=f2tf(v0.y);
        As[0][ar][ac+2]=f2tf(v0.z); As[0][ar][ac+3]=f2tf(v0.w);
        As[0][ar+64][ac+0]=f2tf(v1.x); As[0][ar+64][ac+1]=f2tf(v1.y);
        As[0][ar+64][ac+2]=f2tf(v1.z); As[0][ar+64][ac+3]=f2tf(v1.w);
        float4 w0 = *(const float4*)&Bm[(size_t)br * N + col0 + bc];
        float4 w1 = *(const float4*)&Bm[(size_t)(br + 8) * N + col0 + bc];
        Bs[0][br][bc+0]=f2tf(w0.x); Bs[0][br][bc+1]=f2tf(w0.y);
        Bs[0][br][bc+2]=f2tf(w0.z); Bs[0][br][bc+3]=f2tf(w0.w);
        Bs[0][br+8][bc+0]=f2tf(w1.x); Bs[0][br+8][bc+1]=f2tf(w1.y);
        Bs[0][br+8][bc+2]=f2tf(w1.z); Bs[0][br+8][bc+3]=f2tf(w1.w);
    }
    __syncthreads();

    const int T = K >> 4;
    for (int t = 0; t < T; ++t) {
        const int cur = t & 1;
        float4 pa0, pa1, pb0, pb1;
        if (t + 1 < T) {
            const int k0 = (t + 1) << 4;
            pa0 = *(const float4*)&A[(size_t)(row0 + ar) * K + k0 + ac];
            pa1 = *(const float4*)&A[(size_t)(row0 + ar + 64) * K + k0 + ac];
            pb0 = *(const float4*)&Bm[(size_t)(k0 + br) * N + col0 + bc];
            pb1 = *(const float4*)&Bm[(size_t)(k0 + br + 8) * N + col0 + bc];
        }
        #pragma unroll
        for (int ks = 0; ks < 2; ++ks) {
            const int k8 = ks * 8;
            unsigned af[4][4], bf[4][2];
            #pragma unroll
            for (int mt = 0; mt < 4; ++mt) {
                const int rm = wm * 64 + mt * 16;
                af[mt][0] = As[cur][rm + gid    ][k8 + tig    ];
                af[mt][1] = As[cur][rm + gid + 8][k8 + tig    ];
                af[mt][2] = As[cur][rm + gid    ][k8 + tig + 4];
                af[mt][3] = As[cur][rm + gid + 8][k8 + tig + 4];
            }
            #pragma unroll
            for (int nt = 0; nt < 4; ++nt) {
                const int cn = wn * 32 + nt * 8;
                bf[nt][0] = Bs[cur][k8 + tig    ][cn + gid];
                bf[nt][1] = Bs[cur][k8 + tig + 4][cn + gid];
            }
            #pragma unroll
            for (int mt = 0; mt < 4; ++mt)
                #pragma unroll
                for (int nt = 0; nt < 4; ++nt)
                    mma8(acc[mt][nt], af[mt], bf[nt]);
        }
        if (t + 1 < T) {
            const int nb = cur ^ 1;
            As[nb][ar][ac+0]=f2tf(pa0.x); As[nb][ar][ac+1]=f2tf(pa0.y);
            As[nb][ar][ac+2]=f2tf(pa0.z); As[nb][ar][ac+3]=f2tf(pa0.w);
            As[nb][ar+64][ac+0]=f2tf(pa1.x); As[nb][ar+64][ac+1]=f2tf(pa1.y);
            As[nb][ar+64][ac+2]=f2tf(pa1.z); As[nb][ar+64][ac+3]=f2tf(pa1.w);
            Bs[nb][br][bc+0]=f2tf(pb0.x); Bs[nb][br][bc+1]=f2tf(pb0.y);
            Bs[nb][br][bc+2]=f2tf(pb0.z); Bs[nb][br][bc+3]=f2tf(pb0.w);
            Bs[nb][br+8][bc+0]=f2tf(pb1.x); Bs[nb][br+8][bc+1]=f2tf(pb1.y);
            Bs[nb][br+8][bc+2]=f2tf(pb1.z); Bs[nb][br+8][bc+3]=f2tf(pb1.w);
            __syncthreads();
        }
    }

    #pragma unroll
    for (int mt = 0; mt < 4; ++mt) {
        const int row = row0 + wm * 64 + mt * 16 + gid;
        #pragma unroll
        for (int nt = 0; nt < 4; ++nt) {
            const int col = col0 + wn * 32 + nt * 8 + tig * 2;
            const float b0 = bias[col], b1 = bias[col + 1];
            *(float2*)&C[(size_t)row * N + col] =
                make_float2(acc[mt][nt][0] + b0, acc[mt][nt][1] + b1);
            *(float2*)&C[(size_t)(row + 8) * N + col] =
                make_float2(acc[mt][nt][2] + b0, acc[mt][nt][3] + b1);
        }
    }
}

// ---------------------------------------------------------------
// logits[bh,q,k] = (Q.K^T)*0.125 + min(1, m[q]+m[k]), tensor cores.
// 128x128 tile per block, depth 64 in two chunks of 32, single buffer.
// ---------------------------------------------------------------
__global__ void __launch_bounds__(256) logits_tc(
    const float* __restrict__ Q, const float* __restrict__ Km,
    const float* __restrict__ mask, float* __restrict__ attn)
{
    __shared__ unsigned Qs[128][36];
    __shared__ unsigned Ks[128][36];

    const int tid  = threadIdx.x;
    const int lane = tid & 31;
    const int wid  = tid >> 5;
    const int gid  = lane >> 2;
    const int tig  = lane & 3;
    const int wm   = wid & 1;
    const int wn   = wid >> 1;
    const int bh = blockIdx.z, b = bh >> 4, h = bh & 15;
    const int q0 = blockIdx.y * 128, k0 = blockIdx.x * 128;

    const float* Qb = Q  + (size_t)b * Ss * Dd + h * DEPTH;
    const float* Kb = Km + (size_t)b * Ss * Dd + h * DEPTH;

    float acc[4][4][4] = {};

    #pragma unroll
    for (int c = 0; c < 2; ++c) {
        const int d0 = c * 32;
        if (c) __syncthreads();
        #pragma unroll
        for (int i = 0; i < 4; ++i) {
            const int idx = tid + i * 256;
            const int r = idx >> 3, c4 = (idx & 7) * 4;
            float4 v = *(const float4*)&Qb[(size_t)(q0 + r) * Dd + d0 + c4];
            Qs[r][c4+0]=f2tf(v.x); Qs[r][c4+1]=f2tf(v.y);
            Qs[r][c4+2]=f2tf(v.z); Qs[r][c4+3]=f2tf(v.w);
            float4 w = *(const float4*)&Kb[(size_t)(k0 + r) * Dd + d0 + c4];
            Ks[r][c4+0]=f2tf(w.x); Ks[r][c4+1]=f2tf(w.y);
            Ks[r][c4+2]=f2tf(w.z); Ks[r][c4+3]=f2tf(w.w);
        }
        __syncthreads();
        #pragma unroll
        for (int ks = 0; ks < 4; ++ks) {
            const int k8 = ks * 8;
            unsigned af[4][4], bf[4][2];
            #pragma unroll
            for (int mt = 0; mt < 4; ++mt) {
                const int rm = wm * 64 + mt * 16;
                af[mt][0] = Qs[rm + gid    ][k8 + tig    ];
                af[mt][1] = Qs[rm + gid + 8][k8 + tig    ];
                af[mt][2] = Qs[rm + gid    ][k8 + tig + 4];
                af[mt][3] = Qs[rm + gid + 8][k8 + tig + 4];
            }
            #pragma unroll
            for (int nt = 0; nt < 4; ++nt) {
                const int cn = wn * 32 + nt * 8;
                bf[nt][0] = Ks[cn + gid][k8 + tig    ];
                bf[nt][1] = Ks[cn + gid][k8 + tig + 4];
            }
            #pragma unroll
            for (int mt = 0; mt < 4; ++mt)
                #pragma unroll
                for (int nt = 0; nt < 4; ++nt)
                    mma8(acc[mt][nt], af[mt], bf[nt]);
        }
    }

    const float* mb = mask + b * Ss;
    #pragma unroll
    for (int mt = 0; mt < 4; ++mt) {
        const int row = q0 + wm * 64 + mt * 16 + gid;
        const float mq0 = mb[row], mq1 = mb[row + 8];
        float* o0 = attn + ((size_t)bh * Ss + row) * Ss + k0;
        float* o1 = o0 + (size_t)8 * Ss;
        #pragma unroll
        for (int nt = 0; nt < 4; ++nt) {
            const int col = wn * 32 + nt * 8 + tig * 2;
            const float mk0 = mb[k0 + col], mk1 = mb[k0 + col + 1];
            *(float2*)&o0[col] = make_float2(
                acc[mt][nt][0] * 0.125f + fminf(1.0f, mq0 + mk0),
                acc[mt][nt][1] * 0.125f + fminf(1.0f, mq0 + mk1));
            *(float2*)&o1[col] = make_float2(
                acc[mt][nt][2] * 0.125f + fminf(1.0f, mq1 + mk0),
                acc[mt][nt][3] * 0.125f + fminf(1.0f, mq1 + mk1));
        }
    }
}

// ---------------------------------------------------------------
// In-place softmax over last dim (S=2048). 1 block (256 thr) per row.
// ---------------------------------------------------------------
__global__ void softmax_kernel(float* __restrict__ attn) {
    const size_t row = blockIdx.x;
    float* p = attn + row * (size_t)Ss;
    const int t = threadIdx.x;

    float v[8];
    float mx = -1e30f;
    #pragma unroll
    for (int i = 0; i < 8; i++) {
        v[i] = p[t + 256 * i];
        mx = fmaxf(mx, v[i]);
    }

    __shared__ float red[8];
    #pragma unroll
    for (int o = 16; o; o >>= 1) mx = fmaxf(mx, __shfl_xor_sync(0xffffffffu, mx, o));
    if ((t & 31) == 0) red[t >> 5] = mx;
    __syncthreads();
    mx = red[0];
    #pragma unroll
    for (int i = 1; i < 8; i++) mx = fmaxf(mx, red[i]);
    __syncthreads();

    float sum = 0.0f;
    #pragma unroll
    for (int i = 0; i < 8; i++) {
        v[i] = __expf(v[i] - mx);
        sum += v[i];
    }
    #pragma unroll
    for (int o = 16; o; o >>= 1) sum += __shfl_xor_sync(0xffffffffu, sum, o);
    if ((t & 31) == 0) red[t >> 5] = sum;
    __syncthreads();
    sum = 0.0f;
    #pragma unroll
    for (int i = 0; i < 8; i++) sum += red[i];

    const float inv = 1.0f / sum;
    #pragma unroll
    for (int i = 0; i < 8; i++) p[t + 256 * i] = v[i] * inv;
}

// ---------------------------------------------------------------
// Z[b,q,h*64+n] = sum_k attn[bh,q,k] * V[b,k,h*64+n], tensor cores.
// BM=128 (q), BN=64 (depth), BK=16, warp grid 4x2, warp tile 32x32.
// ---------------------------------------------------------------
__global__ void __launch_bounds__(256) av_tc(
    const float* __restrict__ attn, const float* __restrict__ V,
    float* __restrict__ Z)
{
    __shared__ unsigned As[2][128][20];
    __shared__ unsigned Vs[2][16][72];

    const int tid  = threadIdx.x;
    const int lane = tid & 31;
    const int wid  = tid >> 5;
    const int gid  = lane >> 2;
    const int tig  = lane & 3;
    const int wm   = wid & 3;         // 4 warps over M
    const int wn   = wid >> 2;        // 2 warps over N
    const int bh = blockIdx.y, b = bh >> 4, h = bh & 15;
    const int q0 = blockIdx.x * 128;

    const float* Ab = attn + (size_t)bh * Ss * Ss;
    const float* Vb = V + (size_t)b * Ss * Dd + h * DEPTH;

    const int ar = tid >> 2, ac = (tid & 3) * 4;    // attn rows ar, ar+64
    const int vr = tid >> 4, vc = (tid & 15) * 4;   // V: 16 x 16 float4

    float acc[2][4][4] = {};

    // tile 0
    {
        float4 v0 = *(const float4*)&Ab[(size_t)(q0 + ar) * Ss + ac];
        float4 v1 = *(const float4*)&Ab[(size_t)(q0 + ar + 64) * Ss + ac];
        As[0][ar][ac+0]=f2tf(v0.x); As[0][ar][ac+1]=f2tf(v0.y);
        As[0][ar][ac+2]=f2tf(v0.z); As[0][ar][ac+3]=f2tf(v0.w);
        As[0][ar+64][ac+0]=f2tf(v1.x); As[0][ar+64][ac+1]=f2tf(v1.y);
        As[0][ar+64][ac+2]=f2tf(v1.z); As[0][ar+64][ac+3]=f2tf(v1.w);
        float4 w = *(const float4*)&Vb[(size_t)vr * Dd + vc];
        Vs[0][vr][vc+0]=f2tf(w.x); Vs[0][vr][vc+1]=f2tf(w.y);
        Vs[0][vr][vc+2]=f2tf(w.z); Vs[0][vr][vc+3]=f2tf(w.w);
    }
    __syncthreads();

    const int T = Ss >> 4;   // 128
    for (int t = 0; t < T; ++t) {
        const int cur = t & 1;
        float4 pa0, pa1, pv;
        if (t + 1 < T) {
            const int k0 = (t + 1) << 4;
            pa0 = *(const float4*)&Ab[(size_t)(q0 + ar) * Ss + k0 + ac];
            pa1 = *(const float4*)&Ab[(size_t)(q0 + ar + 64) * Ss + k0 + ac];
            pv  = *(const float4*)&Vb[(size_t)(k0 + vr) * Dd + vc];
        }
        #pragma unroll
        for (int ks = 0; ks < 2; ++ks) {
            const int k8 = ks * 8;
            unsigned af[2][4], bf[4][2];
            #pragma unroll
            for (int mt = 0; mt < 2; ++mt) {
                const int rm = wm * 32 + mt * 16;
                af[mt][0] = As[cur][rm + gid    ][k8 + tig    ];
                af[mt][1] = As[cur][rm + gid + 8][k8 + tig    ];
                af[mt][2] = As[cur][rm + gid    ][k8 + tig + 4];
                af[mt][3] = As[cur][rm + gid + 8][k8 + tig + 4];
            }
            #pragma unroll
            for (int nt = 0; nt < 4; ++nt) {
                const int cn = wn * 32 + nt * 8;
                bf[nt][0] = Vs[cur][k8 + tig    ][cn + gid];
                bf[nt][1] = Vs[cur][k8 + tig + 4][cn + gid];
            }
            #pragma unroll
            for (int mt = 0; mt < 2; ++mt)
                #pragma unroll
                for (int nt = 0; nt < 4; ++nt)
                    mma8(acc[mt][nt], af[mt], bf[nt]);
        }
        if (t + 1 < T) {
            const int nb = cur ^ 1;
            As[nb][ar][ac+0]=f2tf(pa0.x); As[nb][ar][ac+1]=f2tf(pa0.y);
            As[nb][ar][ac+2]=f2tf(pa0.z); As[nb][ar][ac+3]=f2tf(pa0.w);
            As[nb][ar+64][ac+0]=f2tf(pa1.x); As[nb][ar+64][ac+1]=f2tf(pa1.y);
            As[nb][ar+64][ac+2]=f2tf(pa1.z); As[nb][ar+64][ac+3]=f2tf(pa1.w);
            Vs[nb][vr][vc+0]=f2tf(pv.x); Vs[nb][vr][vc+1]=f2tf(pv.y);
            Vs[nb][vr][vc+2]=f2tf(pv.z); Vs[nb][vr][vc+3]=f2tf(pv.w);
            __syncthreads();
        }
    }

    float* Zb = Z + (size_t)b * Ss * Dd + h * DEPTH;
    #pragma unroll
    for (int mt = 0; mt < 2; ++mt) {
        const int row = q0 + wm * 32 + mt * 16 + gid;
        #pragma unroll
        for (int nt = 0; nt < 4; ++nt) {
            const int col = wn * 32 + nt * 8 + tig * 2;
            *(float2*)&Zb[(size_t)row * Dd + col] =
                make_float2(acc[mt][nt][0], acc[mt][nt][1]);
            *(float2*)&Zb[(size_t)(row + 8) * Dd + col] =
                make_float2(acc[mt][nt][2], acc[mt][nt][3]);
        }
    }
}

// ---------------------------------------------------------------
extern "C" void kernel_launch(void* const* d_in, const int* in_sizes, int n_in,
                              void* d_out, int out_size) {
    const float* x    = (const float*)d_in[0];
    const float* mask = (const float*)d_in[1];
    const float* Wq   = (const float*)d_in[2];
    const float* bq   = (const float*)d_in[3];
    const float* Wk   = (const float*)d_in[4];
    const float* bk   = (const float*)d_in[5];
    const float* Wv   = (const float*)d_in[6];
    const float* bv   = (const float*)d_in[7];
    const float* Wo   = (const float*)d_in[8];
    const float* bo   = (const float*)d_in[9];

    float *Qb, *Kb, *Vb, *Zb, *attn_scr, *out_scr;
    cudaGetSymbolAddress((void**)&Qb, g_Q);
    cudaGetSymbolAddress((void**)&Kb, g_K);
    cudaGetSymbolAddress((void**)&Vb, g_V);
    cudaGetSymbolAddress((void**)&Zb, g_Z);
    cudaGetSymbolAddress((void**)&attn_scr, g_attn);
    cudaGetSymbolAddress((void**)&out_scr, g_out);

    float* out_ptr;
    float* attn_ptr;
    const long long osz = (long long)out_size;
    if (osz >= OUT_ELEMS + ATTN_ELEMS) {
        out_ptr  = (float*)d_out;
        attn_ptr = (float*)d_out + OUT_ELEMS;
    } else if (osz >= ATTN_ELEMS) {
        attn_ptr = (float*)d_out;
        out_ptr  = out_scr;
    } else {
        out_ptr  = (float*)d_out;
        attn_ptr = attn_scr;
    }

    const dim3 blk(256);

    // QKV projections (tensor cores)
    {
        dim3 grid(Dd / 128, MROWS / 128);
        gemm_tc<<<grid, blk>>>(x, Wq, bq, Qb, MROWS, Dd, Dd);
        gemm_tc<<<grid, blk>>>(x, Wk, bk, Kb, MROWS, Dd, Dd);
        gemm_tc<<<grid, blk>>>(x, Wv, bv, Vb, MROWS, Dd, Dd);
    }

    // logits + mask (tensor cores)
    {
        dim3 grid(Ss / 128, Ss / 128, Bb * Hh);
        logits_tc<<<grid, blk>>>(Qb, Kb, mask, attn_ptr);
    }

    // softmax rows
    softmax_kernel<<<(unsigned)(Bb * Hh * Ss), blk>>>(attn_ptr);

    // Z = attn @ V (tensor cores)
    {
        dim3 grid(Ss / 128, Bb * Hh);
        av_tc<<<grid, blk>>>(attn_ptr, Vb, Zb);
    }

    // out = Z @ Wo + bo (tensor cores)
    {
        dim3 grid(Dd / 128, MROWS / 128);
        gemm_tc<<<grid, blk>>>(Zb, Wo, bo, out_ptr, MROWS, Dd, Dd);
    }
}

// round 6
// speedup vs baseline: 3.5764x; 1.0498x over previous
#include <cuda_runtime.h>
#include <math.h>

// Problem constants
#define Bb 2
#define Ss 2048
#define Dd 1024
#define Hh 16
#define DEPTH 64
#define MROWS (Bb * Ss)                 // 4096
#define NKBLK (Ss / 128)                // 16 k-blocks per attn row

static const long long OUT_ELEMS  = (long long)Bb * Ss * Dd;          // 4,194,304
static const long long ATTN_ELEMS = (long long)Bb * Hh * Ss * Ss;     // 134,217,728

// ---------------- device scratch (no cudaMalloc allowed) ----------------
__device__ float g_Q[MROWS * Dd];
__device__ float g_K[MROWS * Dd];
__device__ float g_V[MROWS * Dd];
__device__ float g_Z[MROWS * Dd];
__device__ float g_attn[(size_t)Bb * Hh * Ss * Ss];   // 512 MB bss fallback
__device__ float g_out[MROWS * Dd];                   // fallback
__device__ float g_rowpart[(size_t)Bb * Hh * Ss * NKBLK];  // partial row sums
__device__ float g_inv[(size_t)Bb * Hh * Ss];              // 1/rowsum

// ---------------- tf32 helpers ----------------
__device__ __forceinline__ unsigned f2tf(float f) {
    unsigned u;
    asm("cvt.rna.tf32.f32 %0, %1;" : "=r"(u) : "f"(f));
    return u;
}

__device__ __forceinline__ void mma8(float* d, const unsigned* a, const unsigned* b) {
    asm volatile(
        "mma.sync.aligned.m16n8k8.row.col.f32.tf32.tf32.f32 "
        "{%0,%1,%2,%3}, {%4,%5,%6,%7}, {%8,%9}, {%0,%1,%2,%3};\n"
        : "+f"(d[0]), "+f"(d[1]), "+f"(d[2]), "+f"(d[3])
        : "r"(a[0]), "r"(a[1]), "r"(a[2]), "r"(a[3]),
          "r"(b[0]), "r"(b[1]));
}

// ---------------------------------------------------------------
// Tensor-core GEMM: C = A @ B + bias. BM=BN=128, BK=16, 256 thr,
// warp tile 64x32, double buffered. (unchanged from round 3)
// ---------------------------------------------------------------
__device__ __forceinline__ void gemm_body(
    const float* __restrict__ A, const float* __restrict__ Bm,
    const float* __restrict__ bias, float* __restrict__ C,
    int M, int N, int K, int bx, int by)
{
    __shared__ unsigned As[2][128][20];
    __shared__ unsigned Bs[2][16][136];

    const int tid  = threadIdx.x;
    const int lane = tid & 31;
    const int wid  = tid >> 5;
    const int gid  = lane >> 2;
    const int tig  = lane & 3;
    const int wm   = wid & 1;
    const int wn   = wid >> 1;
    const int row0 = by * 128;
    const int col0 = bx * 128;

    const int ar = tid >> 2;
    const int ac = (tid & 3) * 4;
    const int br = tid >> 5;
    const int bc = (tid & 31) * 4;

    float acc[4][4][4] = {};

    {
        float4 v0 = *(const float4*)&A[(size_t)(row0 + ar) * K + ac];
        float4 v1 = *(const float4*)&A[(size_t)(row0 + ar + 64) * K + ac];
        As[0][ar][ac+0]=f2tf(v0.x); As[0][ar][ac+1]=f2tf(v0.y);
        As[0][ar][ac+2]=f2tf(v0.z); As[0][ar][ac+3]=f2tf(v0.w);
        As[0][ar+64][ac+0]=f2tf(v1.x); As[0][ar+64][ac+1]=f2tf(v1.y);
        As[0][ar+64][ac+2]=f2tf(v1.z); As[0][ar+64][ac+3]=f2tf(v1.w);
        float4 w0 = *(const float4*)&Bm[(size_t)br * N + col0 + bc];
        float4 w1 = *(const float4*)&Bm[(size_t)(br + 8) * N + col0 + bc];
        Bs[0][br][bc+0]=f2tf(w0.x); Bs[0][br][bc+1]=f2tf(w0.y);
        Bs[0][br][bc+2]=f2tf(w0.z); Bs[0][br][bc+3]=f2tf(w0.w);
        Bs[0][br+8][bc+0]=f2tf(w1.x); Bs[0][br+8][bc+1]=f2tf(w1.y);
        Bs[0][br+8][bc+2]=f2tf(w1.z); Bs[0][br+8][bc+3]=f2tf(w1.w);
    }
    __syncthreads();

    const int T = K >> 4;
    for (int t = 0; t < T; ++t) {
        const int cur = t & 1;
        float4 pa0, pa1, pb0, pb1;
        if (t + 1 < T) {
            const int k0 = (t + 1) << 4;
            pa0 = *(const float4*)&A[(size_t)(row0 + ar) * K + k0 + ac];
            pa1 = *(const float4*)&A[(size_t)(row0 + ar + 64) * K + k0 + ac];
            pb0 = *(const float4*)&Bm[(size_t)(k0 + br) * N + col0 + bc];
            pb1 = *(const float4*)&Bm[(size_t)(k0 + br + 8) * N + col0 + bc];
        }
        #pragma unroll
        for (int ks = 0; ks < 2; ++ks) {
            const int k8 = ks * 8;
            unsigned af[4][4], bf[4][2];
            #pragma unroll
            for (int mt = 0; mt < 4; ++mt) {
                const int rm = wm * 64 + mt * 16;
                af[mt][0] = As[cur][rm + gid    ][k8 + tig    ];
                af[mt][1] = As[cur][rm + gid + 8][k8 + tig    ];
                af[mt][2] = As[cur][rm + gid    ][k8 + tig + 4];
                af[mt][3] = As[cur][rm + gid + 8][k8 + tig + 4];
            }
            #pragma unroll
            for (int nt = 0; nt < 4; ++nt) {
                const int cn = wn * 32 + nt * 8;
                bf[nt][0] = Bs[cur][k8 + tig    ][cn + gid];
                bf[nt][1] = Bs[cur][k8 + tig + 4][cn + gid];
            }
            #pragma unroll
            for (int mt = 0; mt < 4; ++mt)
                #pragma unroll
                for (int nt = 0; nt < 4; ++nt)
                    mma8(acc[mt][nt], af[mt], bf[nt]);
        }
        if (t + 1 < T) {
            const int nb = cur ^ 1;
            As[nb][ar][ac+0]=f2tf(pa0.x); As[nb][ar][ac+1]=f2tf(pa0.y);
            As[nb][ar][ac+2]=f2tf(pa0.z); As[nb][ar][ac+3]=f2tf(pa0.w);
            As[nb][ar+64][ac+0]=f2tf(pa1.x); As[nb][ar+64][ac+1]=f2tf(pa1.y);
            As[nb][ar+64][ac+2]=f2tf(pa1.z); As[nb][ar+64][ac+3]=f2tf(pa1.w);
            Bs[nb][br][bc+0]=f2tf(pb0.x); Bs[nb][br][bc+1]=f2tf(pb0.y);
            Bs[nb][br][bc+2]=f2tf(pb0.z); Bs[nb][br][bc+3]=f2tf(pb0.w);
            Bs[nb][br+8][bc+0]=f2tf(pb1.x); Bs[nb][br+8][bc+1]=f2tf(pb1.y);
            Bs[nb][br+8][bc+2]=f2tf(pb1.z); Bs[nb][br+8][bc+3]=f2tf(pb1.w);
            __syncthreads();
        }
    }

    #pragma unroll
    for (int mt = 0; mt < 4; ++mt) {
        const int row = row0 + wm * 64 + mt * 16 + gid;
        #pragma unroll
        for (int nt = 0; nt < 4; ++nt) {
            const int col = col0 + wn * 32 + nt * 8 + tig * 2;
            const float b0 = bias[col], b1 = bias[col + 1];
            *(float2*)&C[(size_t)row * N + col] =
                make_float2(acc[mt][nt][0] + b0, acc[mt][nt][1] + b1);
            *(float2*)&C[(size_t)(row + 8) * N + col] =
                make_float2(acc[mt][nt][2] + b0, acc[mt][nt][3] + b1);
        }
    }
}

__global__ void __launch_bounds__(256) gemm_tc(
    const float* __restrict__ A, const float* __restrict__ Bm,
    const float* __restrict__ bias, float* __restrict__ C,
    int M, int N, int K)
{
    gemm_body(A, Bm, bias, C, M, N, K, blockIdx.x, blockIdx.y);
}

// Fused QKV: grid.z selects which projection.
__global__ void __launch_bounds__(256) qkv_tc(
    const float* __restrict__ A,
    const float* __restrict__ W0, const float* __restrict__ W1, const float* __restrict__ W2,
    const float* __restrict__ b0, const float* __restrict__ b1, const float* __restrict__ b2,
    float* __restrict__ O0, float* __restrict__ O1, float* __restrict__ O2)
{
    const int z = blockIdx.z;
    const float* W = (z == 0) ? W0 : (z == 1) ? W1 : W2;
    const float* bv = (z == 0) ? b0 : (z == 1) ? b1 : b2;
    float* O = (z == 0) ? O0 : (z == 1) ? O1 : O2;
    gemm_body(A, W, bv, O, MROWS, Dd, Dd, blockIdx.x, blockIdx.y);
}

// ---------------------------------------------------------------
// logits_exp: attn[bh,q,k] = exp((Q.K^T)*0.125 + min(1,m[q]+m[k]))
// plus deterministic per-(row, kblock) partial sums.
// 512 threads, block 128x128, warp grid 4x4, warp tile 32x32.
// ---------------------------------------------------------------
__global__ void __launch_bounds__(512) logits_exp_tc(
    const float* __restrict__ Q, const float* __restrict__ Km,
    const float* __restrict__ mask, float* __restrict__ attn,
    float* __restrict__ rowpart)
{
    __shared__ unsigned Qs[128][36];
    __shared__ unsigned Ks[128][36];
    __shared__ float rsum[128][4];

    const int tid  = threadIdx.x;
    const int lane = tid & 31;
    const int wid  = tid >> 5;        // 0..15
    const int gid  = lane >> 2;
    const int tig  = lane & 3;
    const int wm   = wid & 3;         // 4 warps over M
    const int wn   = wid >> 2;        // 4 warps over N
    const int bh = blockIdx.z, b = bh >> 4, h = bh & 15;
    const int q0 = blockIdx.y * 128, k0 = blockIdx.x * 128;

    const float* Qb = Q  + (size_t)b * Ss * Dd + h * DEPTH;
    const float* Kb = Km + (size_t)b * Ss * Dd + h * DEPTH;

    float acc[2][4][4] = {};

    #pragma unroll
    for (int c = 0; c < 2; ++c) {
        const int d0 = c * 32;
        if (c) __syncthreads();
        #pragma unroll
        for (int i = 0; i < 2; ++i) {
            const int idx = tid + i * 512;
            const int r = idx >> 3, c4 = (idx & 7) * 4;
            float4 v = *(const float4*)&Qb[(size_t)(q0 + r) * Dd + d0 + c4];
            Qs[r][c4+0]=f2tf(v.x); Qs[r][c4+1]=f2tf(v.y);
            Qs[r][c4+2]=f2tf(v.z); Qs[r][c4+3]=f2tf(v.w);
            float4 w = *(const float4*)&Kb[(size_t)(k0 + r) * Dd + d0 + c4];
            Ks[r][c4+0]=f2tf(w.x); Ks[r][c4+1]=f2tf(w.y);
            Ks[r][c4+2]=f2tf(w.z); Ks[r][c4+3]=f2tf(w.w);
        }
        __syncthreads();
        #pragma unroll
        for (int ks = 0; ks < 4; ++ks) {
            const int k8 = ks * 8;
            unsigned af[2][4], bf[4][2];
            #pragma unroll
            for (int mt = 0; mt < 2; ++mt) {
                const int rm = wm * 32 + mt * 16;
                af[mt][0] = Qs[rm + gid    ][k8 + tig    ];
                af[mt][1] = Qs[rm + gid + 8][k8 + tig    ];
                af[mt][2] = Qs[rm + gid    ][k8 + tig + 4];
                af[mt][3] = Qs[rm + gid + 8][k8 + tig + 4];
            }
            #pragma unroll
            for (int nt = 0; nt < 4; ++nt) {
                const int cn = wn * 32 + nt * 8;
                bf[nt][0] = Ks[cn + gid][k8 + tig    ];
                bf[nt][1] = Ks[cn + gid][k8 + tig + 4];
            }
            #pragma unroll
            for (int mt = 0; mt < 2; ++mt)
                #pragma unroll
                for (int nt = 0; nt < 4; ++nt)
                    mma8(acc[mt][nt], af[mt], bf[nt]);
        }
    }

    const float* mb = mask + b * Ss;
    #pragma unroll
    for (int mt = 0; mt < 2; ++mt) {
        const int lrow = wm * 32 + mt * 16 + gid;
        const int row  = q0 + lrow;
        const float mq0 = mb[row], mq1 = mb[row + 8];
        float* o0 = attn + ((size_t)bh * Ss + row) * Ss + k0;
        float* o1 = o0 + (size_t)8 * Ss;
        float s0 = 0.0f, s1 = 0.0f;
        #pragma unroll
        for (int nt = 0; nt < 4; ++nt) {
            const int col = wn * 32 + nt * 8 + tig * 2;
            const float mk0 = mb[k0 + col], mk1 = mb[k0 + col + 1];
            float e0 = __expf(acc[mt][nt][0] * 0.125f + fminf(1.0f, mq0 + mk0));
            float e1 = __expf(acc[mt][nt][1] * 0.125f + fminf(1.0f, mq0 + mk1));
            float e2 = __expf(acc[mt][nt][2] * 0.125f + fminf(1.0f, mq1 + mk0));
            float e3 = __expf(acc[mt][nt][3] * 0.125f + fminf(1.0f, mq1 + mk1));
            *(float2*)&o0[col] = make_float2(e0, e1);
            *(float2*)&o1[col] = make_float2(e2, e3);
            s0 += e0 + e1;
            s1 += e2 + e3;
        }
        // reduce across the 4 lanes of the quad (same gid, tig 0..3)
        s0 += __shfl_xor_sync(0xffffffffu, s0, 1);
        s0 += __shfl_xor_sync(0xffffffffu, s0, 2);
        s1 += __shfl_xor_sync(0xffffffffu, s1, 1);
        s1 += __shfl_xor_sync(0xffffffffu, s1, 2);
        if (tig == 0) {
            rsum[lrow    ][wn] = s0;
            rsum[lrow + 8][wn] = s1;
        }
    }
    __syncthreads();
    if (tid < 128) {
        float s = rsum[tid][0] + rsum[tid][1] + rsum[tid][2] + rsum[tid][3];
        rowpart[((size_t)bh * Ss + q0 + tid) * NKBLK + blockIdx.x] = s;
    }
}

// ---------------------------------------------------------------
// inv[row] = 1 / sum_kb rowpart[row][kb]   (deterministic order)
// ---------------------------------------------------------------
__global__ void rowsum_inv(const float* __restrict__ part, float* __restrict__ inv) {
    const int r = blockIdx.x * 256 + threadIdx.x;
    const float4* p = (const float4*)(part + (size_t)r * NKBLK);
    float4 a = p[0], b = p[1], c = p[2], d = p[3];
    float s = ((a.x + a.y) + (a.z + a.w)) + ((b.x + b.y) + (b.z + b.w))
            + ((c.x + c.y) + (c.z + c.w)) + ((d.x + d.y) + (d.z + d.w));
    inv[r] = 1.0f / s;
}

// ---------------------------------------------------------------
// av_norm: reads exp-attn, scales by inv[row], writes NORMALIZED attn
// back in place, and computes Z = attn_norm @ V on tensor cores.
// 512 threads, block 128(q) x 64(depth), warp grid 8x2, warp tile 16x32.
// ---------------------------------------------------------------
__global__ void __launch_bounds__(512) av_norm_tc(
    float* __restrict__ attn, const float* __restrict__ V,
    const float* __restrict__ inv, float* __restrict__ Z)
{
    __shared__ unsigned As[2][128][20];
    __shared__ unsigned Vs[2][16][72];

    const int tid  = threadIdx.x;
    const int lane = tid & 31;
    const int wid  = tid >> 5;        // 0..15
    const int gid  = lane >> 2;
    const int tig  = lane & 3;
    const int wm   = wid & 7;         // 8 warps over M (16 rows each)
    const int wn   = wid >> 3;        // 2 warps over N (32 cols each)
    const int bh = blockIdx.y, b = bh >> 4, h = bh & 15;
    const int q0 = blockIdx.x * 128;

    float* Ab = attn + (size_t)bh * Ss * Ss;
    const float* Vb = V + (size_t)b * Ss * Dd + h * DEPTH;

    const int ar = tid >> 2, ac = (tid & 3) * 4;    // 128 rows x 4 float4-cols
    const int vr = tid >> 4, vc = (tid & 15) * 4;   // valid if tid < 256
    const float inv_r = inv[(size_t)bh * Ss + q0 + ar];

    float acc[4][4] = {};

    // tile 0
    {
        float4 a0 = *(const float4*)&Ab[(size_t)(q0 + ar) * Ss + ac];
        a0.x *= inv_r; a0.y *= inv_r; a0.z *= inv_r; a0.w *= inv_r;
        *(float4*)&Ab[(size_t)(q0 + ar) * Ss + ac] = a0;
        As[0][ar][ac+0]=f2tf(a0.x); As[0][ar][ac+1]=f2tf(a0.y);
        As[0][ar][ac+2]=f2tf(a0.z); As[0][ar][ac+3]=f2tf(a0.w);
        if (tid < 256) {
            float4 w = *(const float4*)&Vb[(size_t)vr * Dd + vc];
            Vs[0][vr][vc+0]=f2tf(w.x); Vs[0][vr][vc+1]=f2tf(w.y);
            Vs[0][vr][vc+2]=f2tf(w.z); Vs[0][vr][vc+3]=f2tf(w.w);
        }
    }
    __syncthreads();

    const int T = Ss >> 4;   // 128
    for (int t = 0; t < T; ++t) {
        const int cur = t & 1;
        float4 pa, pv;
        if (t + 1 < T) {
            const int k0 = (t + 1) << 4;
            pa = *(const float4*)&Ab[(size_t)(q0 + ar) * Ss + k0 + ac];
            if (tid < 256)
                pv = *(const float4*)&Vb[(size_t)(k0 + vr) * Dd + vc];
        }
        #pragma unroll
        for (int ks = 0; ks < 2; ++ks) {
            const int k8 = ks * 8;
            unsigned af[4], bf[4][2];
            const int rm = wm * 16;
            af[0] = As[cur][rm + gid    ][k8 + tig    ];
            af[1] = As[cur][rm + gid + 8][k8 + tig    ];
            af[2] = As[cur][rm + gid    ][k8 + tig + 4];
            af[3] = As[cur][rm + gid + 8][k8 + tig + 4];
            #pragma unroll
            for (int nt = 0; nt < 4; ++nt) {
                const int cn = wn * 32 + nt * 8;
                bf[nt][0] = Vs[cur][k8 + tig    ][cn + gid];
                bf[nt][1] = Vs[cur][k8 + tig + 4][cn + gid];
            }
            #pragma unroll
            for (int nt = 0; nt < 4; ++nt)
                mma8(acc[nt], af, bf[nt]);
        }
        if (t + 1 < T) {
            const int nb = cur ^ 1;
            const int k0 = (t + 1) << 4;
            pa.x *= inv_r; pa.y *= inv_r; pa.z *= inv_r; pa.w *= inv_r;
            *(float4*)&Ab[(size_t)(q0 + ar) * Ss + k0 + ac] = pa;
            As[nb][ar][ac+0]=f2tf(pa.x); As[nb][ar][ac+1]=f2tf(pa.y);
            As[nb][ar][ac+2]=f2tf(pa.z); As[nb][ar][ac+3]=f2tf(pa.w);
            if (tid < 256) {
                Vs[nb][vr][vc+0]=f2tf(pv.x); Vs[nb][vr][vc+1]=f2tf(pv.y);
                Vs[nb][vr][vc+2]=f2tf(pv.z); Vs[nb][vr][vc+3]=f2tf(pv.w);
            }
            __syncthreads();
        }
    }

    float* Zb = Z + (size_t)b * Ss * Dd + h * DEPTH;
    const int row = q0 + wm * 16 + gid;
    #pragma unroll
    for (int nt = 0; nt < 4; ++nt) {
        const int col = wn * 32 + nt * 8 + tig * 2;
        *(float2*)&Zb[(size_t)row * Dd + col] = make_float2(acc[nt][0], acc[nt][1]);
        *(float2*)&Zb[(size_t)(row + 8) * Dd + col] = make_float2(acc[nt][2], acc[nt][3]);
    }
}

// ---------------------------------------------------------------
extern "C" void kernel_launch(void* const* d_in, const int* in_sizes, int n_in,
                              void* d_out, int out_size) {
    const float* x    = (const float*)d_in[0];
    const float* mask = (const float*)d_in[1];
    const float* Wq   = (const float*)d_in[2];
    const float* bq   = (const float*)d_in[3];
    const float* Wk   = (const float*)d_in[4];
    const float* bk   = (const float*)d_in[5];
    const float* Wv   = (const float*)d_in[6];
    const float* bv   = (const float*)d_in[7];
    const float* Wo   = (const float*)d_in[8];
    const float* bo   = (const float*)d_in[9];

    float *Qb, *Kb, *Vb, *Zb, *attn_scr, *out_scr, *rowpart, *invp;
    cudaGetSymbolAddress((void**)&Qb, g_Q);
    cudaGetSymbolAddress((void**)&Kb, g_K);
    cudaGetSymbolAddress((void**)&Vb, g_V);
    cudaGetSymbolAddress((void**)&Zb, g_Z);
    cudaGetSymbolAddress((void**)&attn_scr, g_attn);
    cudaGetSymbolAddress((void**)&out_scr, g_out);
    cudaGetSymbolAddress((void**)&rowpart, g_rowpart);
    cudaGetSymbolAddress((void**)&invp, g_inv);

    float* out_ptr;
    float* attn_ptr;
    const long long osz = (long long)out_size;
    if (osz >= OUT_ELEMS + ATTN_ELEMS) {
        out_ptr  = (float*)d_out;
        attn_ptr = (float*)d_out + OUT_ELEMS;
    } else if (osz >= ATTN_ELEMS) {
        attn_ptr = (float*)d_out;
        out_ptr  = out_scr;
    } else {
        out_ptr  = (float*)d_out;
        attn_ptr = attn_scr;
    }

    // QKV projections, fused into one launch (grid.z = which projection)
    {
        dim3 grid(Dd / 128, MROWS / 128, 3);
        qkv_tc<<<grid, 256>>>(x, Wq, Wk, Wv, bq, bk, bv, Qb, Kb, Vb);
    }

    // exp(logits) + partial row sums
    {
        dim3 grid(Ss / 128, Ss / 128, Bb * Hh);
        logits_exp_tc<<<grid, 512>>>(Qb, Kb, mask, attn_ptr, rowpart);
    }

    // 1/rowsum
    rowsum_inv<<<(Bb * Hh * Ss) / 256, 256>>>(rowpart, invp);

    // normalize attn in place + Z = attn @ V
    {
        dim3 grid(Ss / 128, Bb * Hh);
        av_norm_tc<<<grid, 512>>>(attn_ptr, Vb, invp, Zb);
    }

    // out = Z @ Wo + bo
    {
        dim3 grid(Dd / 128, MROWS / 128);
        gemm_tc<<<grid, 256>>>(Zb, Wo, bo, out_ptr, MROWS, Dd, Dd);
    }
}

// round 9
// speedup vs baseline: 3.6715x; 1.0266x over previous
#include <cuda_runtime.h>
#include <math.h>

// Problem constants
#define Bb 2
#define Ss 2048
#define Dd 1024
#define Hh 16
#define DEPTH 64
#define MROWS (Bb * Ss)                 // 4096
#define NKBLK (Ss / 128)                // 16 k-blocks per attn row (pass-1 partials)

static const long long OUT_ELEMS  = (long long)Bb * Ss * Dd;          // 4,194,304
static const long long ATTN_ELEMS = (long long)Bb * Hh * Ss * Ss;     // 134,217,728

// ---------------- device scratch (no cudaMalloc allowed) ----------------
__device__ float g_Q[MROWS * Dd];
__device__ float g_K[MROWS * Dd];
__device__ float g_V[MROWS * Dd];
__device__ float g_Z[MROWS * Dd];
__device__ float g_attn[(size_t)Bb * Hh * Ss * Ss];   // 512 MB bss fallback
__device__ float g_out[MROWS * Dd];                   // fallback
__device__ float g_rowpart[(size_t)Bb * Hh * Ss * NKBLK];  // partial row sums
__device__ float g_inv[(size_t)Bb * Hh * Ss];              // 1/rowsum

// ---------------- tf32 helpers ----------------
__device__ __forceinline__ unsigned f2tf(float f) {
    unsigned u;
    asm("cvt.rna.tf32.f32 %0, %1;" : "=r"(u) : "f"(f));
    return u;
}

__device__ __forceinline__ void mma8(float* d, const unsigned* a, const unsigned* b) {
    asm volatile(
        "mma.sync.aligned.m16n8k8.row.col.f32.tf32.tf32.f32 "
        "{%0,%1,%2,%3}, {%4,%5,%6,%7}, {%8,%9}, {%0,%1,%2,%3};\n"
        : "+f"(d[0]), "+f"(d[1]), "+f"(d[2]), "+f"(d[3])
        : "r"(a[0]), "r"(a[1]), "r"(a[2]), "r"(a[3]),
          "r"(b[0]), "r"(b[1]));
}

// ---------------------------------------------------------------
// Tensor-core GEMM body: C = A @ B + bias. BM=BN=128, BK=16, 256 thr,
// warp tile 64x32, double buffered.
// ---------------------------------------------------------------
__device__ __forceinline__ void gemm_body(
    const float* __restrict__ A, const float* __restrict__ Bm,
    const float* __restrict__ bias, float* __restrict__ C,
    int M, int N, int K, int bx, int by)
{
    __shared__ unsigned As[2][128][20];
    __shared__ unsigned Bs[2][16][136];

    const int tid  = threadIdx.x;
    const int lane = tid & 31;
    const int wid  = tid >> 5;
    const int gid  = lane >> 2;
    const int tig  = lane & 3;
    const int wm   = wid & 1;
    const int wn   = wid >> 1;
    const int row0 = by * 128;
    const int col0 = bx * 128;

    const int ar = tid >> 2;
    const int ac = (tid & 3) * 4;
    const int br = tid >> 5;
    const int bc = (tid & 31) * 4;

    float acc[4][4][4] = {};

    {
        float4 v0 = *(const float4*)&A[(size_t)(row0 + ar) * K + ac];
        float4 v1 = *(const float4*)&A[(size_t)(row0 + ar + 64) * K + ac];
        As[0][ar][ac+0]=f2tf(v0.x); As[0][ar][ac+1]=f2tf(v0.y);
        As[0][ar][ac+2]=f2tf(v0.z); As[0][ar][ac+3]=f2tf(v0.w);
        As[0][ar+64][ac+0]=f2tf(v1.x); As[0][ar+64][ac+1]=f2tf(v1.y);
        As[0][ar+64][ac+2]=f2tf(v1.z); As[0][ar+64][ac+3]=f2tf(v1.w);
        float4 w0 = *(const float4*)&Bm[(size_t)br * N + col0 + bc];
        float4 w1 = *(const float4*)&Bm[(size_t)(br + 8) * N + col0 + bc];
        Bs[0][br][bc+0]=f2tf(w0.x); Bs[0][br][bc+1]=f2tf(w0.y);
        Bs[0][br][bc+2]=f2tf(w0.z); Bs[0][br][bc+3]=f2tf(w0.w);
        Bs[0][br+8][bc+0]=f2tf(w1.x); Bs[0][br+8][bc+1]=f2tf(w1.y);
        Bs[0][br+8][bc+2]=f2tf(w1.z); Bs[0][br+8][bc+3]=f2tf(w1.w);
    }
    __syncthreads();

    const int T = K >> 4;
    for (int t = 0; t < T; ++t) {
        const int cur = t & 1;
        float4 pa0, pa1, pb0, pb1;
        if (t + 1 < T) {
            const int k0 = (t + 1) << 4;
            pa0 = *(const float4*)&A[(size_t)(row0 + ar) * K + k0 + ac];
            pa1 = *(const float4*)&A[(size_t)(row0 + ar + 64) * K + k0 + ac];
            pb0 = *(const float4*)&Bm[(size_t)(k0 + br) * N + col0 + bc];
            pb1 = *(const float4*)&Bm[(size_t)(k0 + br + 8) * N + col0 + bc];
        }
        #pragma unroll
        for (int ks = 0; ks < 2; ++ks) {
            const int k8 = ks * 8;
            unsigned af[4][4], bf[4][2];
            #pragma unroll
            for (int mt = 0; mt < 4; ++mt) {
                const int rm = wm * 64 + mt * 16;
                af[mt][0] = As[cur][rm + gid    ][k8 + tig    ];
                af[mt][1] = As[cur][rm + gid + 8][k8 + tig    ];
                af[mt][2] = As[cur][rm + gid    ][k8 + tig + 4];
                af[mt][3] = As[cur][rm + gid + 8][k8 + tig + 4];
            }
            #pragma unroll
            for (int nt = 0; nt < 4; ++nt) {
                const int cn = wn * 32 + nt * 8;
                bf[nt][0] = Bs[cur][k8 + tig    ][cn + gid];
                bf[nt][1] = Bs[cur][k8 + tig + 4][cn + gid];
            }
            #pragma unroll
            for (int mt = 0; mt < 4; ++mt)
                #pragma unroll
                for (int nt = 0; nt < 4; ++nt)
                    mma8(acc[mt][nt], af[mt], bf[nt]);
        }
        if (t + 1 < T) {
            const int nb = cur ^ 1;
            As[nb][ar][ac+0]=f2tf(pa0.x); As[nb][ar][ac+1]=f2tf(pa0.y);
            As[nb][ar][ac+2]=f2tf(pa0.z); As[nb][ar][ac+3]=f2tf(pa0.w);
            As[nb][ar+64][ac+0]=f2tf(pa1.x); As[nb][ar+64][ac+1]=f2tf(pa1.y);
            As[nb][ar+64][ac+2]=f2tf(pa1.z); As[nb][ar+64][ac+3]=f2tf(pa1.w);
            Bs[nb][br][bc+0]=f2tf(pb0.x); Bs[nb][br][bc+1]=f2tf(pb0.y);
            Bs[nb][br][bc+2]=f2tf(pb0.z); Bs[nb][br][bc+3]=f2tf(pb0.w);
            Bs[nb][br+8][bc+0]=f2tf(pb1.x); Bs[nb][br+8][bc+1]=f2tf(pb1.y);
            Bs[nb][br+8][bc+2]=f2tf(pb1.z); Bs[nb][br+8][bc+3]=f2tf(pb1.w);
            __syncthreads();
        }
    }

    #pragma unroll
    for (int mt = 0; mt < 4; ++mt) {
        const int row = row0 + wm * 64 + mt * 16 + gid;
        #pragma unroll
        for (int nt = 0; nt < 4; ++nt) {
            const int col = col0 + wn * 32 + nt * 8 + tig * 2;
            const float b0 = bias[col], b1 = bias[col + 1];
            *(float2*)&C[(size_t)row * N + col] =
                make_float2(acc[mt][nt][0] + b0, acc[mt][nt][1] + b1);
            *(float2*)&C[(size_t)(row + 8) * N + col] =
                make_float2(acc[mt][nt][2] + b0, acc[mt][nt][3] + b1);
        }
    }
}

__global__ void __launch_bounds__(256) gemm_tc(
    const float* __restrict__ A, const float* __restrict__ Bm,
    const float* __restrict__ bias, float* __restrict__ C,
    int M, int N, int K)
{
    gemm_body(A, Bm, bias, C, M, N, K, blockIdx.x, blockIdx.y);
}

__global__ void __launch_bounds__(256) qkv_tc(
    const float* __restrict__ A,
    const float* __restrict__ W0, const float* __restrict__ W1, const float* __restrict__ W2,
    const float* __restrict__ b0, const float* __restrict__ b1, const float* __restrict__ b2,
    float* __restrict__ O0, float* __restrict__ O1, float* __restrict__ O2)
{
    const int z = blockIdx.z;
    const float* W = (z == 0) ? W0 : (z == 1) ? W1 : W2;
    const float* bv = (z == 0) ? b0 : (z == 1) ? b1 : b2;
    float* O = (z == 0) ? O0 : (z == 1) ? O1 : O2;
    gemm_body(A, W, bv, O, MROWS, Dd, Dd, blockIdx.x, blockIdx.y);
}

// ---------------------------------------------------------------
// PASS 1: row sums of exp(logits) only — no attn store.
// 512 threads, block 128x128, warp grid 4x4, warp tile 32x32.
// ---------------------------------------------------------------
__global__ void __launch_bounds__(512) logits_sums_tc(
    const float* __restrict__ Q, const float* __restrict__ Km,
    const float* __restrict__ mask, float* __restrict__ rowpart)
{
    __shared__ unsigned Qs[128][36];
    __shared__ unsigned Ks[128][36];
    __shared__ float rsum[128][4];

    const int tid  = threadIdx.x;
    const int lane = tid & 31;
    const int wid  = tid >> 5;
    const int gid  = lane >> 2;
    const int tig  = lane & 3;
    const int wm   = wid & 3;
    const int wn   = wid >> 2;
    const int bh = blockIdx.z, b = bh >> 4, h = bh & 15;
    const int q0 = blockIdx.y * 128, k0 = blockIdx.x * 128;

    const float* Qb = Q  + (size_t)b * Ss * Dd + h * DEPTH;
    const float* Kb = Km + (size_t)b * Ss * Dd + h * DEPTH;

    float acc[2][4][4] = {};

    #pragma unroll
    for (int c = 0; c < 2; ++c) {
        const int d0 = c * 32;
        if (c) __syncthreads();
        #pragma unroll
        for (int i = 0; i < 2; ++i) {
            const int idx = tid + i * 512;
            const int r = idx >> 3, c4 = (idx & 7) * 4;
            float4 v = *(const float4*)&Qb[(size_t)(q0 + r) * Dd + d0 + c4];
            Qs[r][c4+0]=f2tf(v.x); Qs[r][c4+1]=f2tf(v.y);
            Qs[r][c4+2]=f2tf(v.z); Qs[r][c4+3]=f2tf(v.w);
            float4 w = *(const float4*)&Kb[(size_t)(k0 + r) * Dd + d0 + c4];
            Ks[r][c4+0]=f2tf(w.x); Ks[r][c4+1]=f2tf(w.y);
            Ks[r][c4+2]=f2tf(w.z); Ks[r][c4+3]=f2tf(w.w);
        }
        __syncthreads();
        #pragma unroll
        for (int ks = 0; ks < 4; ++ks) {
            const int k8 = ks * 8;
            unsigned af[2][4], bf[4][2];
            #pragma unroll
            for (int mt = 0; mt < 2; ++mt) {
                const int rm = wm * 32 + mt * 16;
                af[mt][0] = Qs[rm + gid    ][k8 + tig    ];
                af[mt][1] = Qs[rm + gid + 8][k8 + tig    ];
                af[mt][2] = Qs[rm + gid    ][k8 + tig + 4];
                af[mt][3] = Qs[rm + gid + 8][k8 + tig + 4];
            }
            #pragma unroll
            for (int nt = 0; nt < 4; ++nt) {
                const int cn = wn * 32 + nt * 8;
                bf[nt][0] = Ks[cn + gid][k8 + tig    ];
                bf[nt][1] = Ks[cn + gid][k8 + tig + 4];
            }
            #pragma unroll
            for (int mt = 0; mt < 2; ++mt)
                #pragma unroll
                for (int nt = 0; nt < 4; ++nt)
                    mma8(acc[mt][nt], af[mt], bf[nt]);
        }
    }

    const float* mb = mask + b * Ss;
    #pragma unroll
    for (int mt = 0; mt < 2; ++mt) {
        const int lrow = wm * 32 + mt * 16 + gid;
        const int row  = q0 + lrow;
        const float mq0 = mb[row], mq1 = mb[row + 8];
        float s0 = 0.0f, s1 = 0.0f;
        #pragma unroll
        for (int nt = 0; nt < 4; ++nt) {
            const int col = wn * 32 + nt * 8 + tig * 2;
            const float mk0 = mb[k0 + col], mk1 = mb[k0 + col + 1];
            float e0 = __expf(acc[mt][nt][0] * 0.125f + fminf(1.0f, mq0 + mk0));
            float e1 = __expf(acc[mt][nt][1] * 0.125f + fminf(1.0f, mq0 + mk1));
            float e2 = __expf(acc[mt][nt][2] * 0.125f + fminf(1.0f, mq1 + mk0));
            float e3 = __expf(acc[mt][nt][3] * 0.125f + fminf(1.0f, mq1 + mk1));
            s0 += e0 + e1;
            s1 += e2 + e3;
        }
        s0 += __shfl_xor_sync(0xffffffffu, s0, 1);
        s0 += __shfl_xor_sync(0xffffffffu, s0, 2);
        s1 += __shfl_xor_sync(0xffffffffu, s1, 1);
        s1 += __shfl_xor_sync(0xffffffffu, s1, 2);
        if (tig == 0) {
            rsum[lrow    ][wn] = s0;
            rsum[lrow + 8][wn] = s1;
        }
    }
    __syncthreads();
    if (tid < 128) {
        float s = rsum[tid][0] + rsum[tid][1] + rsum[tid][2] + rsum[tid][3];
        rowpart[((size_t)bh * Ss + q0 + tid) * NKBLK + blockIdx.x] = s;
    }
}

// ---------------------------------------------------------------
// inv[row] = 1 / sum_kb rowpart[row][kb]
// ---------------------------------------------------------------
__global__ void rowsum_inv(const float* __restrict__ part, float* __restrict__ inv) {
    const int r = blockIdx.x * 256 + threadIdx.x;
    const float4* p = (const float4*)(part + (size_t)r * NKBLK);
    float4 a = p[0], b = p[1], c = p[2], d = p[3];
    float s = ((a.x + a.y) + (a.z + a.w)) + ((b.x + b.y) + (b.z + b.w))
            + ((c.x + c.y) + (c.z + c.w)) + ((d.x + d.y) + (d.z + d.w));
    inv[r] = 1.0f / s;
}

// ---------------------------------------------------------------
// PASS 2 (fused): per (bh, q-block 128), loop k in chunks of 64:
//   recompute S = Q.K^T (MMA), p = exp(S*0.125+mask)*inv  (normalized),
//   write p to attn (final output), stage tf32 p in smem,
//   Z += p @ V (MMA). Only 537 MB of attn traffic (the mandatory write).
// 256 threads (8 warps): warp grid 4(q) x 2(k/d), warp tiles 32x32.
// Dynamic smem: Qs[128][68] Ks[64][68] Vs[64][72] Ps[128][68] = 105472 B.
// ---------------------------------------------------------------
#define QS(r,c) smq[(r)*68+(c)]
#define KS(r,c) smk[(r)*68+(c)]
#define VS(r,c) smv[(r)*72+(c)]
#define PS(r,c) smp[(r)*68+(c)]

__global__ void __launch_bounds__(256) attn_pass2(
    const float* __restrict__ Q, const float* __restrict__ Km,
    const float* __restrict__ V, const float* __restrict__ mask,
    const float* __restrict__ inv, float* __restrict__ attn,
    float* __restrict__ Z)
{
    extern __shared__ unsigned smem_dyn[];
    unsigned* smq = smem_dyn;            // [128][68]
    unsigned* smk = smem_dyn + 8704;     // [64][68]
    unsigned* smv = smem_dyn + 13056;    // [64][72]
    unsigned* smp = smem_dyn + 17664;    // [128][68]

    const int tid  = threadIdx.x;
    const int lane = tid & 31;
    const int wid  = tid >> 5;
    const int gid  = lane >> 2;
    const int tig  = lane & 3;
    const int wq   = wid & 3;         // 4 warp-groups over 128 q rows (32 each)
    const int wk   = wid >> 2;        // 2 warp-groups over 64 k cols / 64 d cols
    const int bh = blockIdx.y, b = bh >> 4, h = bh & 15;
    const int q0 = blockIdx.x * 128;

    const float* Qb = Q  + (size_t)b * Ss * Dd + h * DEPTH;
    const float* Kb = Km + (size_t)b * Ss * Dd + h * DEPTH;
    const float* Vb = V  + (size_t)b * Ss * Dd + h * DEPTH;
    const float* mb = mask + b * Ss;

    // load Q tile (128 x 64) as tf32
    #pragma unroll
    for (int i = 0; i < 8; ++i) {
        const int idx = tid + i * 256;
        const int r = idx >> 4, c4 = (idx & 15) * 4;
        float4 v = *(const float4*)&Qb[(size_t)(q0 + r) * Dd + c4];
        QS(r, c4+0)=f2tf(v.x); QS(r, c4+1)=f2tf(v.y);
        QS(r, c4+2)=f2tf(v.z); QS(r, c4+3)=f2tf(v.w);
    }

    // per-thread row constants for the S epilogue
    float inv_r[2][2], mq[2][2];
    #pragma unroll
    for (int mt = 0; mt < 2; ++mt) {
        const int lrow = wq * 32 + mt * 16 + gid;
        inv_r[mt][0] = inv[(size_t)bh * Ss + q0 + lrow];
        inv_r[mt][1] = inv[(size_t)bh * Ss + q0 + lrow + 8];
        mq[mt][0] = mb[q0 + lrow];
        mq[mt][1] = mb[q0 + lrow + 8];
    }

    float acc_z[2][4][4] = {};

    for (int k0 = 0; k0 < Ss; k0 += 64) {
        __syncthreads();   // previous AV done reading Vs/Ps; S done reading Ks
        // cooperative load of K, V chunks (64 x 64 each)
        #pragma unroll
        for (int i = 0; i < 4; ++i) {
            const int idx = tid + i * 256;
            const int r = idx >> 4, c4 = (idx & 15) * 4;
            float4 kv = *(const float4*)&Kb[(size_t)(k0 + r) * Dd + c4];
            KS(r, c4+0)=f2tf(kv.x); KS(r, c4+1)=f2tf(kv.y);
            KS(r, c4+2)=f2tf(kv.z); KS(r, c4+3)=f2tf(kv.w);
            float4 vv = *(const float4*)&Vb[(size_t)(k0 + r) * Dd + c4];
            VS(r, c4+0)=f2tf(vv.x); VS(r, c4+1)=f2tf(vv.y);
            VS(r, c4+2)=f2tf(vv.z); VS(r, c4+3)=f2tf(vv.w);
        }
        __syncthreads();

        // ---- S = Q.K^T (128 x 64), warp patch 32x32 ----
        float acc_s[2][4][4] = {};
        #pragma unroll
        for (int ds = 0; ds < 8; ++ds) {
            const int d8 = ds * 8;
            unsigned af[2][4], bf[4][2];
            #pragma unroll
            for (int mt = 0; mt < 2; ++mt) {
                const int rm = wq * 32 + mt * 16;
                af[mt][0] = QS(rm + gid    , d8 + tig    );
                af[mt][1] = QS(rm + gid + 8, d8 + tig    );
                af[mt][2] = QS(rm + gid    , d8 + tig + 4);
                af[mt][3] = QS(rm + gid + 8, d8 + tig + 4);
            }
            #pragma unroll
            for (int nt = 0; nt < 4; ++nt) {
                const int cn = wk * 32 + nt * 8;
                bf[nt][0] = KS(cn + gid, d8 + tig    );
                bf[nt][1] = KS(cn + gid, d8 + tig + 4);
            }
            #pragma unroll
            for (int mt = 0; mt < 2; ++mt)
                #pragma unroll
                for (int nt = 0; nt < 4; ++nt)
                    mma8(acc_s[mt][nt], af[mt], bf[nt]);
        }

        // ---- epilogue: p = exp(s*0.125 + mask)*inv; write attn + stage Ps ----
        #pragma unroll
        for (int mt = 0; mt < 2; ++mt) {
            const int lrow = wq * 32 + mt * 16 + gid;
            const int row  = q0 + lrow;
            float* o0 = attn + ((size_t)bh * Ss + row) * Ss + k0;
            float* o1 = o0 + (size_t)8 * Ss;
            #pragma unroll
            for (int nt = 0; nt < 4; ++nt) {
                const int col = wk * 32 + nt * 8 + tig * 2;
                const float mk0 = mb[k0 + col], mk1 = mb[k0 + col + 1];
                float e0 = __expf(acc_s[mt][nt][0] * 0.125f + fminf(1.0f, mq[mt][0] + mk0)) * inv_r[mt][0];
                float e1 = __expf(acc_s[mt][nt][1] * 0.125f + fminf(1.0f, mq[mt][0] + mk1)) * inv_r[mt][0];
                float e2 = __expf(acc_s[mt][nt][2] * 0.125f + fminf(1.0f, mq[mt][1] + mk0)) * inv_r[mt][1];
                float e3 = __expf(acc_s[mt][nt][3] * 0.125f + fminf(1.0f, mq[mt][1] + mk1)) * inv_r[mt][1];
                *(float2*)&o0[col] = make_float2(e0, e1);
                *(float2*)&o1[col] = make_float2(e2, e3);
                PS(lrow    , col    ) = f2tf(e0);
                PS(lrow    , col + 1) = f2tf(e1);
                PS(lrow + 8, col    ) = f2tf(e2);
                PS(lrow + 8, col + 1) = f2tf(e3);
            }
        }
        __syncthreads();

        // ---- Z += P (128 x 64) @ V (64 x 64), warp patch 32x32 ----
        #pragma unroll
        for (int ks = 0; ks < 8; ++ks) {
            const int kk = ks * 8;
            unsigned af[2][4], bf[4][2];
            #pragma unroll
            for (int mt = 0; mt < 2; ++mt) {
                const int rm = wq * 32 + mt * 16;
                af[mt][0] = PS(rm + gid    , kk + tig    );
                af[mt][1] = PS(rm + gid + 8, kk + tig    );
                af[mt][2] = PS(rm + gid    , kk + tig + 4);
                af[mt][3] = PS(rm + gid + 8, kk + tig + 4);
            }
            #pragma unroll
            for (int nt = 0; nt < 4; ++nt) {
                const int cn = wk * 32 + nt * 8;
                bf[nt][0] = VS(kk + tig    , cn + gid);
                bf[nt][1] = VS(kk + tig + 4, cn + gid);
            }
            #pragma unroll
            for (int mt = 0; mt < 2; ++mt)
                #pragma unroll
                for (int nt = 0; nt < 4; ++nt)
                    mma8(acc_z[mt][nt], af[mt], bf[nt]);
        }
    }

    // Z epilogue
    float* Zb = Z + (size_t)b * Ss * Dd + h * DEPTH;
    #pragma unroll
    for (int mt = 0; mt < 2; ++mt) {
        const int row = q0 + wq * 32 + mt * 16 + gid;
        #pragma unroll
        for (int nt = 0; nt < 4; ++nt) {
            const int col = wk * 32 + nt * 8 + tig * 2;
            *(float2*)&Zb[(size_t)row * Dd + col] =
                make_float2(acc_z[mt][nt][0], acc_z[mt][nt][1]);
            *(float2*)&Zb[(size_t)(row + 8) * Dd + col] =
                make_float2(acc_z[mt][nt][2], acc_z[mt][nt][3]);
        }
    }
}

// ---------------------------------------------------------------
extern "C" void kernel_launch(void* const* d_in, const int* in_sizes, int n_in,
                              void* d_out, int out_size) {
    const float* x    = (const float*)d_in[0];
    const float* mask = (const float*)d_in[1];
    const float* Wq   = (const float*)d_in[2];
    const float* bq   = (const float*)d_in[3];
    const float* Wk   = (const float*)d_in[4];
    const float* bk   = (const float*)d_in[5];
    const float* Wv   = (const float*)d_in[6];
    const float* bv   = (const float*)d_in[7];
    const float* Wo   = (const float*)d_in[8];
    const float* bo   = (const float*)d_in[9];

    float *Qb, *Kb, *Vb, *Zb, *attn_scr, *out_scr, *rowpart, *invp;
    cudaGetSymbolAddress((void**)&Qb, g_Q);
    cudaGetSymbolAddress((void**)&Kb, g_K);
    cudaGetSymbolAddress((void**)&Vb, g_V);
    cudaGetSymbolAddress((void**)&Zb, g_Z);
    cudaGetSymbolAddress((void**)&attn_scr, g_attn);
    cudaGetSymbolAddress((void**)&out_scr, g_out);
    cudaGetSymbolAddress((void**)&rowpart, g_rowpart);
    cudaGetSymbolAddress((void**)&invp, g_inv);

    float* out_ptr;
    float* attn_ptr;
    const long long osz = (long long)out_size;
    if (osz >= OUT_ELEMS + ATTN_ELEMS) {
        out_ptr  = (float*)d_out;
        attn_ptr = (float*)d_out + OUT_ELEMS;
    } else if (osz >= ATTN_ELEMS) {
        attn_ptr = (float*)d_out;
        out_ptr  = out_scr;
    } else {
        out_ptr  = (float*)d_out;
        attn_ptr = attn_scr;
    }

    const int PASS2_SMEM = 105472;
    cudaFuncSetAttribute(attn_pass2,
                         cudaFuncAttributeMaxDynamicSharedMemorySize, PASS2_SMEM);

    // QKV projections, fused into one launch (grid.z = which projection)
    {
        dim3 grid(Dd / 128, MROWS / 128, 3);
        qkv_tc<<<grid, 256>>>(x, Wq, Wk, Wv, bq, bk, bv, Qb, Kb, Vb);
    }

    // pass 1: row sums of exp(logits)  (no big store)
    {
        dim3 grid(Ss / 128, Ss / 128, Bb * Hh);
        logits_sums_tc<<<grid, 512>>>(Qb, Kb, mask, rowpart);
    }

    // 1/rowsum
    rowsum_inv<<<(Bb * Hh * Ss) / 256, 256>>>(rowpart, invp);

    // pass 2: recompute S, write normalized attn, Z = attn @ V
    {
        dim3 grid(Ss / 128, Bb * Hh);
        attn_pass2<<<grid, 256, PASS2_SMEM>>>(Qb, Kb, Vb, mask, invp, attn_ptr, Zb);
    }

    // out = Z @ Wo + bo
    {
        dim3 grid(Dd / 128, MROWS / 128);
        gemm_tc<<<grid, 256>>>(Zb, Wo, bo, out_ptr, MROWS, Dd, Dd);
    }
}